// round 4
// baseline (speedup 1.0000x reference)
#include <cuda_runtime.h>
#include <cstdint>

#define N_NODE 100000        // N_USER == N_ITEM == 100000
#define NEDGE  1000000
#define C      128
#define CC     (C * C)
#define NC     ((size_t)N_NODE * C)

// ---------------- device scratch (allowed: __device__ globals) ----------------
__device__ __align__(16) float g_xu[NC];          // user features after layer 0
__device__ __align__(16) float g_xi[NC];          // item features after layer 0
__device__ __align__(16) float g_agg[3][NC];      // 0: ui->item, 1: iu->user, 2: uu->user
__device__ __align__(16) int   g_cnt[3 * N_NODE];
__device__ __align__(16) float g_inv[3 * N_NODE];

// ---------------- tiny utility kernels ----------------
__global__ void zero_k(float4* __restrict__ p, long n4) {
    long i = (long)blockIdx.x * blockDim.x + threadIdx.x;
    long st = (long)gridDim.x * blockDim.x;
    float4 z = make_float4(0.f, 0.f, 0.f, 0.f);
    for (; i < n4; i += st) p[i] = z;
}

__global__ void count_k(const int* __restrict__ dst, int* __restrict__ cnt, int E) {
    int i = blockIdx.x * blockDim.x + threadIdx.x;
    int st = gridDim.x * blockDim.x;
    for (; i < E; i += st) atomicAdd(cnt + dst[i], 1);
}

__global__ void inv_k(const int* __restrict__ cnt, float* __restrict__ inv, int n) {
    int i = blockIdx.x * blockDim.x + threadIdx.x;
    if (i < n) {
        int c = cnt[i];
        inv[i] = 1.0f / (float)(c > 1 ? c : 1);
    }
}

// ---------------- edge scatter: one warp per edge, vector reduction ----------------
__global__ void __launch_bounds__(256) scatter_k(
    const float* __restrict__ x, const int* __restrict__ ei,
    float* __restrict__ agg, int E)
{
    int lane = threadIdx.x & 31;
    int w = (blockIdx.x * blockDim.x + threadIdx.x) >> 5;
    int nw = (gridDim.x * blockDim.x) >> 5;
    for (int e = w; e < E; e += nw) {
        int s = __ldg(ei + e);           // src node
        int d = __ldg(ei + E + e);       // dst node
        float4 v = __ldg((const float4*)(x + (size_t)s * C) + lane);
        float* p = agg + (size_t)d * C + (size_t)lane * 4;
        asm volatile("red.global.add.v4.f32 [%0], {%1,%2,%3,%4};"
                     :: "l"(p), "f"(v.x), "f"(v.y), "f"(v.z), "f"(v.w)
                     : "memory");
    }
}

// ---------------- fused multi-term GEMM + bias + LayerNorm + ReLU ----------------
// out[n,:] = relu(LN( sum_t (A_t[n,:] * scale_t(n)) @ W_t  + bias0 + bias1 ))
// Block: 256 threads, BM=64 nodes. Warp w owns nodes w*8..w*8+7; lane owns cols lane*4..+3.
template <int NTERMS>
__global__ void __launch_bounds__(256) gemm_ln_relu(
    const float* __restrict__ A0, const float* __restrict__ inv0, const float* __restrict__ W0,
    const float* __restrict__ A1, const float* __restrict__ inv1, const float* __restrict__ W1,
    const float* __restrict__ A2, const float* __restrict__ inv2, const float* __restrict__ W2,
    const float* __restrict__ A3, const float* __restrict__ inv3, const float* __restrict__ W3,
    const float* __restrict__ bias0, const float* __restrict__ bias1,
    const float* __restrict__ lnw, const float* __restrict__ lnb,
    float* __restrict__ out, int N)
{
    extern __shared__ float smem[];
    float* sA = smem;              // 64 x 128
    float* sW = smem + 64 * C;     // 128 x 128
    float4* sA4 = (float4*)sA;
    float4* sW4 = (float4*)sW;

    const int t = threadIdx.x;
    const int warp = t >> 5;
    const int lane = t & 31;
    const int nodeBase = blockIdx.x * 64;

    const float* As[4]   = {A0, A1, A2, A3};
    const float* invs[4] = {inv0, inv1, inv2, inv3};
    const float* Ws[4]   = {W0, W1, W2, W3};

    float acc[8][4];
#pragma unroll
    for (int j = 0; j < 8; ++j) {
        acc[j][0] = 0.f; acc[j][1] = 0.f; acc[j][2] = 0.f; acc[j][3] = 0.f;
    }

#pragma unroll 1
    for (int term = 0; term < NTERMS; ++term) {
        const float* A = As[term];
        const float* inv = invs[term];
        const float4* W4 = (const float4*)Ws[term];

        __syncthreads();   // protect previous iteration's smem reads
        // stage W: 128x128 f32 = 4096 float4, 16 per thread
#pragma unroll
        for (int i = 0; i < 16; ++i) sW4[t + i * 256] = W4[t + i * 256];
        // stage A tile (with mean scaling): 64x128 f32 = 2048 float4, 8 per thread
#pragma unroll
        for (int i = 0; i < 8; ++i) {
            int f = t + i * 256;
            int r = f >> 5;                // row within tile (32 float4 per row)
            int node = nodeBase + r;
            float4 v = make_float4(0.f, 0.f, 0.f, 0.f);
            if (node < N) {
                v = __ldg((const float4*)(A + (size_t)node * C) + (f & 31));
                float s = inv ? __ldg(inv + node) : 1.0f;
                v.x *= s; v.y *= s; v.z *= s; v.w *= s;
            }
            sA4[f] = v;
        }
        __syncthreads();

#pragma unroll 4
        for (int k = 0; k < C; ++k) {
            float4 w = sW4[k * 32 + lane];
#pragma unroll
            for (int j = 0; j < 8; ++j) {
                float a = sA[(warp * 8 + j) * C + k];
                acc[j][0] += a * w.x;
                acc[j][1] += a * w.y;
                acc[j][2] += a * w.z;
                acc[j][3] += a * w.w;
            }
        }
    }

    // epilogue: bias + LayerNorm + ReLU
    float4 bv = make_float4(0.f, 0.f, 0.f, 0.f);
    if (bias0) {
        float4 b = __ldg((const float4*)bias0 + lane);
        bv.x += b.x; bv.y += b.y; bv.z += b.z; bv.w += b.w;
    }
    if (bias1) {
        float4 b = __ldg((const float4*)bias1 + lane);
        bv.x += b.x; bv.y += b.y; bv.z += b.z; bv.w += b.w;
    }
    float4 gw = __ldg((const float4*)lnw + lane);
    float4 gb = __ldg((const float4*)lnb + lane);

#pragma unroll 1
    for (int j = 0; j < 8; ++j) {
        int node = nodeBase + warp * 8 + j;
        if (node >= N) break;    // uniform across warp
        float v0 = acc[j][0] + bv.x;
        float v1 = acc[j][1] + bv.y;
        float v2 = acc[j][2] + bv.z;
        float v3 = acc[j][3] + bv.w;
        float s  = v0 + v1 + v2 + v3;
        float sq = v0 * v0 + v1 * v1 + v2 * v2 + v3 * v3;
#pragma unroll
        for (int o = 16; o > 0; o >>= 1) {
            s  += __shfl_xor_sync(0xffffffffu, s, o);
            sq += __shfl_xor_sync(0xffffffffu, sq, o);
        }
        float mu  = s * (1.0f / C);
        float var = sq * (1.0f / C) - mu * mu;
        float r   = rsqrtf(var + 1e-5f);
        float4 o4;
        o4.x = fmaxf((v0 - mu) * r * gw.x + gb.x, 0.f);
        o4.y = fmaxf((v1 - mu) * r * gw.y + gb.y, 0.f);
        o4.z = fmaxf((v2 - mu) * r * gw.z + gb.z, 0.f);
        o4.w = fmaxf((v3 - mu) * r * gw.w + gb.w, 0.f);
        *((float4*)(out + (size_t)node * C) + lane) = o4;
    }
}

// ---------------- host launcher ----------------
extern "C" void kernel_launch(void* const* d_in, const int* in_sizes, int n_in,
                              void* d_out, int out_size)
{
    const float* x_user = (const float*)d_in[0];
    const float* x_item = (const float*)d_in[1];
    const int*   ei_ui  = (const int*)d_in[2];
    const int*   ei_iu  = (const int*)d_in[3];
    const int*   ei_uu  = (const int*)d_in[4];
    const float* Wl     = (const float*)d_in[5];
    const float* bl     = (const float*)d_in[6];
    const float* Wr     = (const float*)d_in[7];
    const float* ln_w   = (const float*)d_in[8];
    const float* ln_b   = (const float*)d_in[9];
    float* out = (float*)d_out;

    void *pxu_, *pxi_, *pagg_, *pcnt_, *pinv_;
    cudaGetSymbolAddress(&pxu_, g_xu);
    cudaGetSymbolAddress(&pxi_, g_xi);
    cudaGetSymbolAddress(&pagg_, g_agg);
    cudaGetSymbolAddress(&pcnt_, g_cnt);
    cudaGetSymbolAddress(&pinv_, g_inv);
    float* pxu  = (float*)pxu_;
    float* pxi  = (float*)pxi_;
    float* pagg = (float*)pagg_;
    int*   pcnt = (int*)pcnt_;
    float* pinv = (float*)pinv_;

    const int smem_bytes = (64 * C + C * C) * (int)sizeof(float);   // 96 KB
    cudaFuncSetAttribute((const void*)gemm_ln_relu<2>,
                         cudaFuncAttributeMaxDynamicSharedMemorySize, smem_bytes);
    cudaFuncSetAttribute((const void*)gemm_ln_relu<4>,
                         cudaFuncAttributeMaxDynamicSharedMemorySize, smem_bytes);

    // degree counts (edges identical across layers -> compute once)
    zero_k<<<256, 256>>>((float4*)pcnt, (long)(3 * N_NODE) / 4);
    count_k<<<2048, 256>>>(ei_ui + NEDGE, pcnt + 0 * N_NODE, NEDGE);
    count_k<<<2048, 256>>>(ei_iu + NEDGE, pcnt + 1 * N_NODE, NEDGE);
    count_k<<<2048, 256>>>(ei_uu + NEDGE, pcnt + 2 * N_NODE, NEDGE);
    inv_k<<<(3 * N_NODE + 255) / 256, 256>>>(pcnt, pinv, 3 * N_NODE);

    const int gemm_blocks = (N_NODE + 63) / 64;

    for (int l = 0; l < 2; ++l) {
        const float* xu_src = (l == 0) ? x_user : pxu;
        const float* xi_src = (l == 0) ? x_item : pxi;
        float* outu = (l == 0) ? pxu : out;
        float* outi = (l == 0) ? pxi : out + NC;

        // zero all three agg buffers
        zero_k<<<4096, 256>>>((float4*)pagg, (long)(3 * NC) / 4);

        // scatter per edge type
        scatter_k<<<8192, 256>>>(xu_src, ei_ui, pagg + 0 * NC, NEDGE);  // user->item
        scatter_k<<<8192, 256>>>(xi_src, ei_iu, pagg + 1 * NC, NEDGE);  // item->user
        scatter_k<<<8192, 256>>>(xu_src, ei_uu, pagg + 2 * NC, NEDGE);  // user->user

        // item output: mean_ui @ Wl[l,0] + bl[l,0] + xi @ Wr[l,0] -> LN(l,item=1) -> ReLU
        gemm_ln_relu<2><<<gemm_blocks, 256, smem_bytes>>>(
            pagg + 0 * NC, pinv + 0 * N_NODE, Wl + (size_t)(l * 3 + 0) * CC,
            xi_src,        nullptr,           Wr + (size_t)(l * 3 + 0) * CC,
            nullptr, nullptr, nullptr,
            nullptr, nullptr, nullptr,
            bl + (size_t)(l * 3 + 0) * C, nullptr,
            ln_w + (size_t)(l * 2 + 1) * C, ln_b + (size_t)(l * 2 + 1) * C,
            outi, N_NODE);

        // user output: mean_iu@Wl[l,1] + bl[l,1] + xu@Wr[l,1]
        //            + mean_uu@Wl[l,2] + bl[l,2] + xu@Wr[l,2] -> LN(l,user=0) -> ReLU
        gemm_ln_relu<4><<<gemm_blocks, 256, smem_bytes>>>(
            pagg + 1 * NC, pinv + 1 * N_NODE, Wl + (size_t)(l * 3 + 1) * CC,
            xu_src,        nullptr,           Wr + (size_t)(l * 3 + 1) * CC,
            pagg + 2 * NC, pinv + 2 * N_NODE, Wl + (size_t)(l * 3 + 2) * CC,
            xu_src,        nullptr,           Wr + (size_t)(l * 3 + 2) * CC,
            bl + (size_t)(l * 3 + 1) * C, bl + (size_t)(l * 3 + 2) * C,
            ln_w + (size_t)(l * 2 + 0) * C, ln_b + (size_t)(l * 2 + 0) * C,
            outu, N_NODE);
    }
}

// round 5
// speedup vs baseline: 1.0033x; 1.0033x over previous
#include <cuda_runtime.h>
#include <cstdint>

#define N_NODE 100000        // N_USER == N_ITEM == 100000
#define NEDGE  1000000
#define C      128
#define CC     (C * C)
#define NC     ((size_t)N_NODE * C)

// ---------------- device scratch (allowed: __device__ globals) ----------------
__device__ __align__(16) float g_xu[NC];          // user features after layer 0
__device__ __align__(16) float g_xi[NC];          // item features after layer 0
__device__ __align__(16) float g_agg[3][NC];      // 0: ui->item, 1: iu->user, 2: uu->user
__device__ __align__(16) int   g_cnt[3 * N_NODE];
__device__ __align__(16) float g_inv[3 * N_NODE];

// ---------------- tiny utility kernels ----------------
__global__ void zero_k(float4* __restrict__ p, long n4) {
    long i = (long)blockIdx.x * blockDim.x + threadIdx.x;
    long st = (long)gridDim.x * blockDim.x;
    float4 z = make_float4(0.f, 0.f, 0.f, 0.f);
    for (; i < n4; i += st) p[i] = z;
}

__global__ void count_k(const int* __restrict__ dst, int* __restrict__ cnt, int E) {
    int i = blockIdx.x * blockDim.x + threadIdx.x;
    int st = gridDim.x * blockDim.x;
    for (; i < E; i += st) atomicAdd(cnt + dst[i], 1);
}

__global__ void inv_k(const int* __restrict__ cnt, float* __restrict__ inv, int n) {
    int i = blockIdx.x * blockDim.x + threadIdx.x;
    if (i < n) {
        int c = cnt[i];
        inv[i] = 1.0f / (float)(c > 1 ? c : 1);
    }
}

// ---------------- edge scatter: one warp per edge, vector reduction ----------------
__global__ void __launch_bounds__(256) scatter_k(
    const float* __restrict__ x, const int* __restrict__ ei,
    float* __restrict__ agg, int E)
{
    int lane = threadIdx.x & 31;
    int w = (blockIdx.x * blockDim.x + threadIdx.x) >> 5;
    int nw = (gridDim.x * blockDim.x) >> 5;
    for (int e = w; e < E; e += nw) {
        int s = __ldg(ei + e);           // src node
        int d = __ldg(ei + E + e);       // dst node
        float4 v = __ldg((const float4*)(x + (size_t)s * C) + lane);
        float* p = agg + (size_t)d * C + (size_t)lane * 4;
        asm volatile("red.global.add.v4.f32 [%0], {%1,%2,%3,%4};"
                     :: "l"(p), "f"(v.x), "f"(v.y), "f"(v.z), "f"(v.w)
                     : "memory");
    }
}

// ---------------- fused multi-term GEMM + bias + LayerNorm + ReLU ----------------
// out[n,:] = relu(LN( sum_t (A_t[n,:] * scale_t(n)) @ W_t  + bias0 + bias1 ))
// Block: 256 threads, BM=64 nodes. Warp w owns nodes w*8..w*8+7; lane owns cols lane*4..+3.
template <int NTERMS>
__global__ void __launch_bounds__(256) gemm_ln_relu(
    const float* __restrict__ A0, const float* __restrict__ inv0, const float* __restrict__ W0,
    const float* __restrict__ A1, const float* __restrict__ inv1, const float* __restrict__ W1,
    const float* __restrict__ A2, const float* __restrict__ inv2, const float* __restrict__ W2,
    const float* __restrict__ A3, const float* __restrict__ inv3, const float* __restrict__ W3,
    const float* __restrict__ bias0, const float* __restrict__ bias1,
    const float* __restrict__ lnw, const float* __restrict__ lnb,
    float* __restrict__ out, int N)
{
    extern __shared__ float smem[];
    float* sA = smem;              // 64 x 128
    float* sW = smem + 64 * C;     // 128 x 128
    float4* sA4 = (float4*)sA;
    float4* sW4 = (float4*)sW;

    const int t = threadIdx.x;
    const int warp = t >> 5;
    const int lane = t & 31;
    const int nodeBase = blockIdx.x * 64;

    const float* As[4]   = {A0, A1, A2, A3};
    const float* invs[4] = {inv0, inv1, inv2, inv3};
    const float* Ws[4]   = {W0, W1, W2, W3};

    float acc[8][4];
#pragma unroll
    for (int j = 0; j < 8; ++j) {
        acc[j][0] = 0.f; acc[j][1] = 0.f; acc[j][2] = 0.f; acc[j][3] = 0.f;
    }

#pragma unroll 1
    for (int term = 0; term < NTERMS; ++term) {
        const float* A = As[term];
        const float* inv = invs[term];
        const float4* W4 = (const float4*)Ws[term];

        __syncthreads();   // protect previous iteration's smem reads
        // stage W: 128x128 f32 = 4096 float4, 16 per thread
#pragma unroll
        for (int i = 0; i < 16; ++i) sW4[t + i * 256] = W4[t + i * 256];
        // stage A tile (with mean scaling): 64x128 f32 = 2048 float4, 8 per thread
#pragma unroll
        for (int i = 0; i < 8; ++i) {
            int f = t + i * 256;
            int r = f >> 5;                // row within tile (32 float4 per row)
            int node = nodeBase + r;
            float4 v = make_float4(0.f, 0.f, 0.f, 0.f);
            if (node < N) {
                v = __ldg((const float4*)(A + (size_t)node * C) + (f & 31));
                float s = inv ? __ldg(inv + node) : 1.0f;
                v.x *= s; v.y *= s; v.z *= s; v.w *= s;
            }
            sA4[f] = v;
        }
        __syncthreads();

#pragma unroll 4
        for (int k = 0; k < C; ++k) {
            float4 w = sW4[k * 32 + lane];
#pragma unroll
            for (int j = 0; j < 8; ++j) {
                float a = sA[(warp * 8 + j) * C + k];
                acc[j][0] += a * w.x;
                acc[j][1] += a * w.y;
                acc[j][2] += a * w.z;
                acc[j][3] += a * w.w;
            }
        }
    }

    // epilogue: bias + LayerNorm + ReLU
    float4 bv = make_float4(0.f, 0.f, 0.f, 0.f);
    if (bias0) {
        float4 b = __ldg((const float4*)bias0 + lane);
        bv.x += b.x; bv.y += b.y; bv.z += b.z; bv.w += b.w;
    }
    if (bias1) {
        float4 b = __ldg((const float4*)bias1 + lane);
        bv.x += b.x; bv.y += b.y; bv.z += b.z; bv.w += b.w;
    }
    float4 gw = __ldg((const float4*)lnw + lane);
    float4 gb = __ldg((const float4*)lnb + lane);

#pragma unroll 1
    for (int j = 0; j < 8; ++j) {
        int node = nodeBase + warp * 8 + j;
        if (node >= N) break;    // uniform across warp
        float v0 = acc[j][0] + bv.x;
        float v1 = acc[j][1] + bv.y;
        float v2 = acc[j][2] + bv.z;
        float v3 = acc[j][3] + bv.w;
        float s  = v0 + v1 + v2 + v3;
        float sq = v0 * v0 + v1 * v1 + v2 * v2 + v3 * v3;
#pragma unroll
        for (int o = 16; o > 0; o >>= 1) {
            s  += __shfl_xor_sync(0xffffffffu, s, o);
            sq += __shfl_xor_sync(0xffffffffu, sq, o);
        }
        float mu  = s * (1.0f / C);
        float var = sq * (1.0f / C) - mu * mu;
        float r   = rsqrtf(var + 1e-5f);
        float4 o4;
        o4.x = fmaxf((v0 - mu) * r * gw.x + gb.x, 0.f);
        o4.y = fmaxf((v1 - mu) * r * gw.y + gb.y, 0.f);
        o4.z = fmaxf((v2 - mu) * r * gw.z + gb.z, 0.f);
        o4.w = fmaxf((v3 - mu) * r * gw.w + gb.w, 0.f);
        *((float4*)(out + (size_t)node * C) + lane) = o4;
    }
}

// ---------------- host launcher ----------------
extern "C" void kernel_launch(void* const* d_in, const int* in_sizes, int n_in,
                              void* d_out, int out_size)
{
    const float* x_user = (const float*)d_in[0];
    const float* x_item = (const float*)d_in[1];
    const int*   ei_ui  = (const int*)d_in[2];
    const int*   ei_iu  = (const int*)d_in[3];
    const int*   ei_uu  = (const int*)d_in[4];
    const float* Wl     = (const float*)d_in[5];
    const float* bl     = (const float*)d_in[6];
    const float* Wr     = (const float*)d_in[7];
    const float* ln_w   = (const float*)d_in[8];
    const float* ln_b   = (const float*)d_in[9];
    float* out = (float*)d_out;

    void *pxu_, *pxi_, *pagg_, *pcnt_, *pinv_;
    cudaGetSymbolAddress(&pxu_, g_xu);
    cudaGetSymbolAddress(&pxi_, g_xi);
    cudaGetSymbolAddress(&pagg_, g_agg);
    cudaGetSymbolAddress(&pcnt_, g_cnt);
    cudaGetSymbolAddress(&pinv_, g_inv);
    float* pxu  = (float*)pxu_;
    float* pxi  = (float*)pxi_;
    float* pagg = (float*)pagg_;
    int*   pcnt = (int*)pcnt_;
    float* pinv = (float*)pinv_;

    const int smem_bytes = (64 * C + C * C) * (int)sizeof(float);   // 96 KB
    cudaFuncSetAttribute((const void*)gemm_ln_relu<2>,
                         cudaFuncAttributeMaxDynamicSharedMemorySize, smem_bytes);
    cudaFuncSetAttribute((const void*)gemm_ln_relu<4>,
                         cudaFuncAttributeMaxDynamicSharedMemorySize, smem_bytes);

    // degree counts (edges identical across layers -> compute once)
    zero_k<<<256, 256>>>((float4*)pcnt, (long)(3 * N_NODE) / 4);
    count_k<<<2048, 256>>>(ei_ui + NEDGE, pcnt + 0 * N_NODE, NEDGE);
    count_k<<<2048, 256>>>(ei_iu + NEDGE, pcnt + 1 * N_NODE, NEDGE);
    count_k<<<2048, 256>>>(ei_uu + NEDGE, pcnt + 2 * N_NODE, NEDGE);
    inv_k<<<(3 * N_NODE + 255) / 256, 256>>>(pcnt, pinv, 3 * N_NODE);

    const int gemm_blocks = (N_NODE + 63) / 64;

    for (int l = 0; l < 2; ++l) {
        const float* xu_src = (l == 0) ? x_user : pxu;
        const float* xi_src = (l == 0) ? x_item : pxi;
        float* outu = (l == 0) ? pxu : out;
        float* outi = (l == 0) ? pxi : out + NC;

        // zero all three agg buffers
        zero_k<<<4096, 256>>>((float4*)pagg, (long)(3 * NC) / 4);

        // scatter per edge type
        scatter_k<<<8192, 256>>>(xu_src, ei_ui, pagg + 0 * NC, NEDGE);  // user->item
        scatter_k<<<8192, 256>>>(xi_src, ei_iu, pagg + 1 * NC, NEDGE);  // item->user
        scatter_k<<<8192, 256>>>(xu_src, ei_uu, pagg + 2 * NC, NEDGE);  // user->user

        // item output: mean_ui @ Wl[l,0] + bl[l,0] + xi @ Wr[l,0] -> LN(l,item=1) -> ReLU
        gemm_ln_relu<2><<<gemm_blocks, 256, smem_bytes>>>(
            pagg + 0 * NC, pinv + 0 * N_NODE, Wl + (size_t)(l * 3 + 0) * CC,
            xi_src,        nullptr,           Wr + (size_t)(l * 3 + 0) * CC,
            nullptr, nullptr, nullptr,
            nullptr, nullptr, nullptr,
            bl + (size_t)(l * 3 + 0) * C, nullptr,
            ln_w + (size_t)(l * 2 + 1) * C, ln_b + (size_t)(l * 2 + 1) * C,
            outi, N_NODE);

        // user output: mean_iu@Wl[l,1] + bl[l,1] + xu@Wr[l,1]
        //            + mean_uu@Wl[l,2] + bl[l,2] + xu@Wr[l,2] -> LN(l,user=0) -> ReLU
        gemm_ln_relu<4><<<gemm_blocks, 256, smem_bytes>>>(
            pagg + 1 * NC, pinv + 1 * N_NODE, Wl + (size_t)(l * 3 + 1) * CC,
            xu_src,        nullptr,           Wr + (size_t)(l * 3 + 1) * CC,
            pagg + 2 * NC, pinv + 2 * N_NODE, Wl + (size_t)(l * 3 + 2) * CC,
            xu_src,        nullptr,           Wr + (size_t)(l * 3 + 2) * CC,
            bl + (size_t)(l * 3 + 1) * C, bl + (size_t)(l * 3 + 2) * C,
            ln_w + (size_t)(l * 2 + 0) * C, ln_b + (size_t)(l * 2 + 0) * C,
            outu, N_NODE);
    }
}

// round 6
// speedup vs baseline: 1.0084x; 1.0050x over previous
#include <cuda_runtime.h>
#include <cstdint>

#define N_NODE 100000        // N_USER == N_ITEM == 100000
#define NEDGE  1000000
#define C      128
#define CC     (C * C)
#define NC     ((size_t)N_NODE * C)

// ---------------- device scratch (allowed: __device__ globals) ----------------
__device__ __align__(16) float g_xu[NC];          // user features after layer 0
__device__ __align__(16) float g_xi[NC];          // item features after layer 0
__device__ __align__(16) float g_agg[3][NC];      // 0: ui->item, 1: iu->user, 2: uu->user
__device__ __align__(16) int   g_cnt[3 * N_NODE];
__device__ __align__(16) float g_inv[3 * N_NODE];

// ---------------- tiny utility kernels ----------------
__global__ void zero_k(float4* __restrict__ p, long n4) {
    long i = (long)blockIdx.x * blockDim.x + threadIdx.x;
    long st = (long)gridDim.x * blockDim.x;
    float4 z = make_float4(0.f, 0.f, 0.f, 0.f);
    for (; i < n4; i += st) p[i] = z;
}

__global__ void count_k(const int* __restrict__ dst, int* __restrict__ cnt, int E) {
    int i = blockIdx.x * blockDim.x + threadIdx.x;
    int st = gridDim.x * blockDim.x;
    for (; i < E; i += st) atomicAdd(cnt + dst[i], 1);
}

__global__ void inv_k(const int* __restrict__ cnt, float* __restrict__ inv, int n) {
    int i = blockIdx.x * blockDim.x + threadIdx.x;
    if (i < n) {
        int c = cnt[i];
        inv[i] = 1.0f / (float)(c > 1 ? c : 1);
    }
}

// ---------------- edge scatter: one warp per edge, vector reduction ----------------
__global__ void __launch_bounds__(256) scatter_k(
    const float* __restrict__ x, const int* __restrict__ ei,
    float* __restrict__ agg, int E)
{
    int lane = threadIdx.x & 31;
    int w = (blockIdx.x * blockDim.x + threadIdx.x) >> 5;
    int nw = (gridDim.x * blockDim.x) >> 5;
    for (int e = w; e < E; e += nw) {
        int s = __ldg(ei + e);           // src node
        int d = __ldg(ei + E + e);       // dst node
        float4 v = __ldg((const float4*)(x + (size_t)s * C) + lane);
        float* p = agg + (size_t)d * C + (size_t)lane * 4;
        asm volatile("red.global.add.v4.f32 [%0], {%1,%2,%3,%4};"
                     :: "l"(p), "f"(v.x), "f"(v.y), "f"(v.z), "f"(v.w)
                     : "memory");
    }
}

// ---------------- fused multi-term GEMM + bias + LayerNorm + ReLU ----------------
// out[n,:] = relu(LN( sum_t (A_t[n,:] * scale_t(n)) @ W_t  + bias0 + bias1 ))
// Block: 256 threads, BM=64 nodes. Warp w owns nodes w*8..w*8+7; lane owns cols lane*4..+3.
template <int NTERMS>
__global__ void __launch_bounds__(256) gemm_ln_relu(
    const float* __restrict__ A0, const float* __restrict__ inv0, const float* __restrict__ W0,
    const float* __restrict__ A1, const float* __restrict__ inv1, const float* __restrict__ W1,
    const float* __restrict__ A2, const float* __restrict__ inv2, const float* __restrict__ W2,
    const float* __restrict__ A3, const float* __restrict__ inv3, const float* __restrict__ W3,
    const float* __restrict__ bias0, const float* __restrict__ bias1,
    const float* __restrict__ lnw, const float* __restrict__ lnb,
    float* __restrict__ out, int N)
{
    extern __shared__ float smem[];
    float* sA = smem;              // 64 x 128
    float* sW = smem + 64 * C;     // 128 x 128
    float4* sA4 = (float4*)sA;
    float4* sW4 = (float4*)sW;

    const int t = threadIdx.x;
    const int warp = t >> 5;
    const int lane = t & 31;
    const int nodeBase = blockIdx.x * 64;

    const float* As[4]   = {A0, A1, A2, A3};
    const float* invs[4] = {inv0, inv1, inv2, inv3};
    const float* Ws[4]   = {W0, W1, W2, W3};

    float acc[8][4];
#pragma unroll
    for (int j = 0; j < 8; ++j) {
        acc[j][0] = 0.f; acc[j][1] = 0.f; acc[j][2] = 0.f; acc[j][3] = 0.f;
    }

#pragma unroll 1
    for (int term = 0; term < NTERMS; ++term) {
        const float* A = As[term];
        const float* inv = invs[term];
        const float4* W4 = (const float4*)Ws[term];

        __syncthreads();   // protect previous iteration's smem reads
        // stage W: 128x128 f32 = 4096 float4, 16 per thread
#pragma unroll
        for (int i = 0; i < 16; ++i) sW4[t + i * 256] = W4[t + i * 256];
        // stage A tile (with mean scaling): 64x128 f32 = 2048 float4, 8 per thread
#pragma unroll
        for (int i = 0; i < 8; ++i) {
            int f = t + i * 256;
            int r = f >> 5;                // row within tile (32 float4 per row)
            int node = nodeBase + r;
            float4 v = make_float4(0.f, 0.f, 0.f, 0.f);
            if (node < N) {
                v = __ldg((const float4*)(A + (size_t)node * C) + (f & 31));
                float s = inv ? __ldg(inv + node) : 1.0f;
                v.x *= s; v.y *= s; v.z *= s; v.w *= s;
            }
            sA4[f] = v;
        }
        __syncthreads();

#pragma unroll 4
        for (int k = 0; k < C; ++k) {
            float4 w = sW4[k * 32 + lane];
#pragma unroll
            for (int j = 0; j < 8; ++j) {
                float a = sA[(warp * 8 + j) * C + k];
                acc[j][0] += a * w.x;
                acc[j][1] += a * w.y;
                acc[j][2] += a * w.z;
                acc[j][3] += a * w.w;
            }
        }
    }

    // epilogue: bias + LayerNorm + ReLU
    float4 bv = make_float4(0.f, 0.f, 0.f, 0.f);
    if (bias0) {
        float4 b = __ldg((const float4*)bias0 + lane);
        bv.x += b.x; bv.y += b.y; bv.z += b.z; bv.w += b.w;
    }
    if (bias1) {
        float4 b = __ldg((const float4*)bias1 + lane);
        bv.x += b.x; bv.y += b.y; bv.z += b.z; bv.w += b.w;
    }
    float4 gw = __ldg((const float4*)lnw + lane);
    float4 gb = __ldg((const float4*)lnb + lane);

#pragma unroll 1
    for (int j = 0; j < 8; ++j) {
        int node = nodeBase + warp * 8 + j;
        if (node >= N) break;    // uniform across warp
        float v0 = acc[j][0] + bv.x;
        float v1 = acc[j][1] + bv.y;
        float v2 = acc[j][2] + bv.z;
        float v3 = acc[j][3] + bv.w;
        float s  = v0 + v1 + v2 + v3;
        float sq = v0 * v0 + v1 * v1 + v2 * v2 + v3 * v3;
#pragma unroll
        for (int o = 16; o > 0; o >>= 1) {
            s  += __shfl_xor_sync(0xffffffffu, s, o);
            sq += __shfl_xor_sync(0xffffffffu, sq, o);
        }
        float mu  = s * (1.0f / C);
        float var = sq * (1.0f / C) - mu * mu;
        float r   = rsqrtf(var + 1e-5f);
        float4 o4;
        o4.x = fmaxf((v0 - mu) * r * gw.x + gb.x, 0.f);
        o4.y = fmaxf((v1 - mu) * r * gw.y + gb.y, 0.f);
        o4.z = fmaxf((v2 - mu) * r * gw.z + gb.z, 0.f);
        o4.w = fmaxf((v3 - mu) * r * gw.w + gb.w, 0.f);
        *((float4*)(out + (size_t)node * C) + lane) = o4;
    }
}

// ---------------- host launcher ----------------
extern "C" void kernel_launch(void* const* d_in, const int* in_sizes, int n_in,
                              void* d_out, int out_size)
{
    const float* x_user = (const float*)d_in[0];
    const float* x_item = (const float*)d_in[1];
    const int*   ei_ui  = (const int*)d_in[2];
    const int*   ei_iu  = (const int*)d_in[3];
    const int*   ei_uu  = (const int*)d_in[4];
    const float* Wl     = (const float*)d_in[5];
    const float* bl     = (const float*)d_in[6];
    const float* Wr     = (const float*)d_in[7];
    const float* ln_w   = (const float*)d_in[8];
    const float* ln_b   = (const float*)d_in[9];
    float* out = (float*)d_out;

    void *pxu_, *pxi_, *pagg_, *pcnt_, *pinv_;
    cudaGetSymbolAddress(&pxu_, g_xu);
    cudaGetSymbolAddress(&pxi_, g_xi);
    cudaGetSymbolAddress(&pagg_, g_agg);
    cudaGetSymbolAddress(&pcnt_, g_cnt);
    cudaGetSymbolAddress(&pinv_, g_inv);
    float* pxu  = (float*)pxu_;
    float* pxi  = (float*)pxi_;
    float* pagg = (float*)pagg_;
    int*   pcnt = (int*)pcnt_;
    float* pinv = (float*)pinv_;

    const int smem_bytes = (64 * C + C * C) * (int)sizeof(float);   // 96 KB
    cudaFuncSetAttribute((const void*)gemm_ln_relu<2>,
                         cudaFuncAttributeMaxDynamicSharedMemorySize, smem_bytes);
    cudaFuncSetAttribute((const void*)gemm_ln_relu<4>,
                         cudaFuncAttributeMaxDynamicSharedMemorySize, smem_bytes);

    // degree counts (edges identical across layers -> compute once)
    zero_k<<<256, 256>>>((float4*)pcnt, (long)(3 * N_NODE) / 4);
    count_k<<<2048, 256>>>(ei_ui + NEDGE, pcnt + 0 * N_NODE, NEDGE);
    count_k<<<2048, 256>>>(ei_iu + NEDGE, pcnt + 1 * N_NODE, NEDGE);
    count_k<<<2048, 256>>>(ei_uu + NEDGE, pcnt + 2 * N_NODE, NEDGE);
    inv_k<<<(3 * N_NODE + 255) / 256, 256>>>(pcnt, pinv, 3 * N_NODE);

    const int gemm_blocks = (N_NODE + 63) / 64;

    for (int l = 0; l < 2; ++l) {
        const float* xu_src = (l == 0) ? x_user : pxu;
        const float* xi_src = (l == 0) ? x_item : pxi;
        float* outu = (l == 0) ? pxu : out;
        float* outi = (l == 0) ? pxi : out + NC;

        // zero all three agg buffers
        zero_k<<<4096, 256>>>((float4*)pagg, (long)(3 * NC) / 4);

        // scatter per edge type
        scatter_k<<<8192, 256>>>(xu_src, ei_ui, pagg + 0 * NC, NEDGE);  // user->item
        scatter_k<<<8192, 256>>>(xi_src, ei_iu, pagg + 1 * NC, NEDGE);  // item->user
        scatter_k<<<8192, 256>>>(xu_src, ei_uu, pagg + 2 * NC, NEDGE);  // user->user

        // item output: mean_ui @ Wl[l,0] + bl[l,0] + xi @ Wr[l,0] -> LN(l,item=1) -> ReLU
        gemm_ln_relu<2><<<gemm_blocks, 256, smem_bytes>>>(
            pagg + 0 * NC, pinv + 0 * N_NODE, Wl + (size_t)(l * 3 + 0) * CC,
            xi_src,        nullptr,           Wr + (size_t)(l * 3 + 0) * CC,
            nullptr, nullptr, nullptr,
            nullptr, nullptr, nullptr,
            bl + (size_t)(l * 3 + 0) * C, nullptr,
            ln_w + (size_t)(l * 2 + 1) * C, ln_b + (size_t)(l * 2 + 1) * C,
            outi, N_NODE);

        // user output: mean_iu@Wl[l,1] + bl[l,1] + xu@Wr[l,1]
        //            + mean_uu@Wl[l,2] + bl[l,2] + xu@Wr[l,2] -> LN(l,user=0) -> ReLU
        gemm_ln_relu<4><<<gemm_blocks, 256, smem_bytes>>>(
            pagg + 1 * NC, pinv + 1 * N_NODE, Wl + (size_t)(l * 3 + 1) * CC,
            xu_src,        nullptr,           Wr + (size_t)(l * 3 + 1) * CC,
            pagg + 2 * NC, pinv + 2 * N_NODE, Wl + (size_t)(l * 3 + 2) * CC,
            xu_src,        nullptr,           Wr + (size_t)(l * 3 + 2) * CC,
            bl + (size_t)(l * 3 + 1) * C, bl + (size_t)(l * 3 + 2) * C,
            ln_w + (size_t)(l * 2 + 0) * C, ln_b + (size_t)(l * 2 + 0) * C,
            outu, N_NODE);
    }
}

// round 8
// speedup vs baseline: 1.0857x; 1.0767x over previous
#include <cuda_runtime.h>
#include <cstdint>

#define N_NODE 100000        // N_USER == N_ITEM == 100000
#define NEDGE  1000000
#define C      128
#define CC     (C * C)
#define NC     ((size_t)N_NODE * C)

// ---------------- device scratch (allowed: __device__ globals) ----------------
__device__ __align__(16) float g_xu[NC];          // user features after layer 0
__device__ __align__(16) float g_xi[NC];          // item features after layer 0
__device__ __align__(16) float g_agg[3][NC];      // 0: ui->item, 1: iu->user, 2: uu->user
__device__ __align__(16) int   g_cnt[3 * N_NODE];
__device__ __align__(16) float g_inv[3 * N_NODE];
__device__ __align__(16) float g_wsum[2 * CC];    // Wr[l,1]+Wr[l,2] per layer

// ---------------- tiny utility kernels ----------------
__global__ void zero_k(float4* __restrict__ p, long n4) {
    long i = (long)blockIdx.x * blockDim.x + threadIdx.x;
    long st = (long)gridDim.x * blockDim.x;
    float4 z = make_float4(0.f, 0.f, 0.f, 0.f);
    for (; i < n4; i += st) p[i] = z;
}

__global__ void count_k(const int* __restrict__ dst, int* __restrict__ cnt, int E) {
    int i = blockIdx.x * blockDim.x + threadIdx.x;
    int st = gridDim.x * blockDim.x;
    for (; i < E; i += st) atomicAdd(cnt + dst[i], 1);
}

__global__ void inv_k(const int* __restrict__ cnt, float* __restrict__ inv, int n) {
    int i = blockIdx.x * blockDim.x + threadIdx.x;
    if (i < n) {
        int c = cnt[i];
        inv[i] = 1.0f / (float)(c > 1 ? c : 1);
    }
}

__global__ void addW_k(const float* __restrict__ a, const float* __restrict__ b,
                       float* __restrict__ o, int n) {
    int i = blockIdx.x * blockDim.x + threadIdx.x;
    if (i < n) o[i] = a[i] + b[i];
}

// ---------------- edge scatter: one warp per edge, vector reduction ----------------
__global__ void __launch_bounds__(256) scatter_k(
    const float* __restrict__ x, const int* __restrict__ ei,
    float* __restrict__ agg, int E)
{
    int lane = threadIdx.x & 31;
    int w = (blockIdx.x * blockDim.x + threadIdx.x) >> 5;
    int nw = (gridDim.x * blockDim.x) >> 5;
    for (int e = w; e < E; e += nw) {
        int s = __ldg(ei + e);           // src node
        int d = __ldg(ei + E + e);       // dst node
        float4 v = __ldg((const float4*)(x + (size_t)s * C) + lane);
        float* p = agg + (size_t)d * C + (size_t)lane * 4;
        asm volatile("red.global.add.v4.f32 [%0], {%1,%2,%3,%4};"
                     :: "l"(p), "f"(v.x), "f"(v.y), "f"(v.z), "f"(v.w)
                     : "memory");
    }
}

// ================ tf32 mma.sync GEMM + bias + LayerNorm + ReLU ================
// D[m,n] = sum_terms (A_t[m,:] * inv_t(m)) @ W_t[:,n], CTA tile 128x128, K=128.
// 8 warps, grid 2M x 4N; each warp 64x32 via m16n8k8.row.col.f32.tf32.tf32.f32.
// Accumulators live in registers across terms. A/B staged in fragment order so
// every fragment load is a conflict-free LDS.128 / LDS.64.

__device__ __forceinline__ uint32_t f2tf32(float x) {
    uint32_t o; asm("cvt.rna.tf32.f32 %0, %1;" : "=r"(o) : "f"(x)); return o;
}

#define MMA_TF32(d, a, b)                                                       \
    asm volatile("mma.sync.aligned.m16n8k8.row.col.f32.tf32.tf32.f32 "          \
                 "{%0,%1,%2,%3}, {%4,%5,%6,%7}, {%8,%9}, {%0,%1,%2,%3};"        \
                 : "+f"((d)[0]), "+f"((d)[1]), "+f"((d)[2]), "+f"((d)[3])       \
                 : "r"((a).x), "r"((a).y), "r"((a).z), "r"((a).w),              \
                   "r"((b).x), "r"((b).y))

// SMEM layout (bytes)
#define SM_A     0          // 64KB: A fragments  [ks][mt][lane] x uint4
#define SM_B     65536      // 64KB: B fragments  [ks][nt][lane] x uint2
#define SM_PART  131072     // 128 rows x 4 warps x float2 = 4KB
#define SM_STAT  135168     // 128 x float2 (mu, rs) = 1KB
#define SM_BIAS  136192     // 128 f32
#define SM_LNW   136704
#define SM_LNB   137216
#define GEMM_SMEM 137728

#define GEMM_GRID 782       // ceil(100000 / 128)

// Stage A tile [128m x 128k] into fragment order, tf32-rounded, mean-scaled.
// Element (m,k) -> a-slot: l = (m&7)*4 + (k&3), slot = ((m>>3)&1) | (((k>>2)&1)<<1)
// uint32 idx = ((ks*8 + mt)*32 + l)*4 + slot,  ks=k>>3, mt=m>>4.
__device__ __forceinline__ void stage_A(uint32_t* sA, const float* __restrict__ A,
                                        const float* __restrict__ inv,
                                        int nodeBase, int N, int t)
{
#pragma unroll 4
    for (int i = 0; i < 16; ++i) {
        int f = t + i * 256;              // 0..4095 float4 slots
        int m = f >> 5, k4 = f & 31;
        int node = nodeBase + m;
        float4 v = make_float4(0.f, 0.f, 0.f, 0.f);
        if (node < N) {
            v = __ldg((const float4*)(A + (size_t)node * C) + k4);
            if (inv) { float s = __ldg(inv + node); v.x *= s; v.y *= s; v.z *= s; v.w *= s; }
        }
        int ks = k4 >> 1;                 // k = 4*k4+e, e<4 -> k>>3 = k4>>1
        int mt = m >> 4;
        int slot = ((m >> 3) & 1) | ((k4 & 1) << 1);   // (k>>2)&1 == k4&1
        int base = ((ks * 8 + mt) * 32 + ((m & 7) << 2)) * 4 + slot;
        sA[base + 0 * 4] = f2tf32(v.x);
        sA[base + 1 * 4] = f2tf32(v.y);
        sA[base + 2 * 4] = f2tf32(v.z);
        sA[base + 3 * 4] = f2tf32(v.w);
    }
}

// Stage B = W [128k x 128n] (row-major) into fragment order, tf32-rounded.
// Element (k,n) -> b-slot: l = (n&7)*4 + (k&3), slot = (k>>2)&1
// uint32 idx = ((ks*16 + nt)*32 + l)*2 + slot,  ks=k>>3, nt=n>>3.
__device__ __forceinline__ void stage_B(uint32_t* sB, const float* __restrict__ W, int t)
{
#pragma unroll 4
    for (int i = 0; i < 16; ++i) {
        int f = t + i * 256;              // 0..4095 float4 slots
        int k = f >> 5, n4 = f & 31;
        float4 w = __ldg((const float4*)W + f);
        int ks = k >> 3;
        int nt = n4 >> 1;                 // n = 4*n4+e -> n>>3 = n4>>1
        int slot = (k >> 2) & 1;
        int n0_7 = (n4 & 1) << 2;         // n&7 base within octet
        int base = ((ks * 16 + nt) * 32) * 2 + (k & 3) * 2 + slot;
        sB[base + (n0_7 + 0) * 8] = f2tf32(w.x);
        sB[base + (n0_7 + 1) * 8] = f2tf32(w.y);
        sB[base + (n0_7 + 2) * 8] = f2tf32(w.z);
        sB[base + (n0_7 + 3) * 8] = f2tf32(w.w);
    }
}

template <int NTERMS>
__global__ void __launch_bounds__(256) gemm_mma(
    const float* __restrict__ A0, const float* __restrict__ inv0, const float* __restrict__ W0,
    const float* __restrict__ A1, const float* __restrict__ inv1, const float* __restrict__ W1,
    const float* __restrict__ A2, const float* __restrict__ inv2, const float* __restrict__ W2,
    const float* __restrict__ bias0, const float* __restrict__ bias1,
    const float* __restrict__ lnw, const float* __restrict__ lnb,
    float* __restrict__ out, int N)
{
    extern __shared__ char smem[];
    uint32_t* sA = (uint32_t*)(smem + SM_A);
    uint32_t* sB = (uint32_t*)(smem + SM_B);
    float2* sPart = (float2*)(smem + SM_PART);
    float2* sStat = (float2*)(smem + SM_STAT);
    float* sBias  = (float*)(smem + SM_BIAS);
    float* sLnw   = (float*)(smem + SM_LNW);
    float* sLnb   = (float*)(smem + SM_LNB);

    const int t = threadIdx.x;
    const int warp = t >> 5;
    const int lane = t & 31;
    const int wm = warp >> 2;     // 0..1  (M half)
    const int wn = warp & 3;      // 0..3  (N quarter)
    const int nodeBase = blockIdx.x * 128;

    if (t < 128) {
        float b = bias0 ? __ldg(bias0 + t) : 0.f;
        if (bias1) b += __ldg(bias1 + t);
        sBias[t] = b;
        sLnw[t] = __ldg(lnw + t);
        sLnb[t] = __ldg(lnb + t);
    }

    const float* As[3]   = {A0, A1, A2};
    const float* invs[3] = {inv0, inv1, inv2};
    const float* Ws[3]   = {W0, W1, W2};

    float acc[4][4][4];
#pragma unroll
    for (int a = 0; a < 4; ++a)
#pragma unroll
        for (int b = 0; b < 4; ++b)
#pragma unroll
            for (int c = 0; c < 4; ++c) acc[a][b][c] = 0.f;

    const uint4* sA4 = (const uint4*)sA;
    const uint2* sB2 = (const uint2*)sB;

#pragma unroll 1
    for (int term = 0; term < NTERMS; ++term) {
        if (term > 0) __syncthreads();    // all warps done reading previous tiles
        stage_A(sA, As[term], invs[term], nodeBase, N, t);
        stage_B(sB, Ws[term], t);
        __syncthreads();

#pragma unroll 1
        for (int ks = 0; ks < 16; ++ks) {
            uint4 af[4];
            uint2 bf[4];
#pragma unroll
            for (int mt = 0; mt < 4; ++mt)
                af[mt] = sA4[(ks * 8 + wm * 4 + mt) * 32 + lane];
#pragma unroll
            for (int nt = 0; nt < 4; ++nt)
                bf[nt] = sB2[(ks * 16 + wn * 4 + nt) * 32 + lane];
#pragma unroll
            for (int mt = 0; mt < 4; ++mt)
#pragma unroll
                for (int nt = 0; nt < 4; ++nt)
                    MMA_TF32(acc[mt][nt], af[mt], bf[nt]);
        }
    }

    // ---------------- epilogue: bias + LayerNorm + ReLU ----------------
    // Thread owns rows (wm*4+mt)*16 + hi*8 + lane/4, cols (wn*4+nt)*8 + (lane&3)*2 + e.
#pragma unroll
    for (int mt = 0; mt < 4; ++mt) {
#pragma unroll
        for (int hi = 0; hi < 2; ++hi) {
            float s = 0.f, q = 0.f;
#pragma unroll
            for (int nt = 0; nt < 4; ++nt) {
#pragma unroll
                for (int e = 0; e < 2; ++e) {
                    int col = (wn * 4 + nt) * 8 + (lane & 3) * 2 + e;
                    float v = acc[mt][nt][hi * 2 + e] + sBias[col];
                    s += v; q += v * v;
                }
            }
            s += __shfl_xor_sync(0xffffffffu, s, 1);
            q += __shfl_xor_sync(0xffffffffu, q, 1);
            s += __shfl_xor_sync(0xffffffffu, s, 2);
            q += __shfl_xor_sync(0xffffffffu, q, 2);
            if ((lane & 3) == 0) {
                int row = (wm * 4 + mt) * 16 + hi * 8 + (lane >> 2);
                sPart[row * 4 + wn] = make_float2(s, q);
            }
        }
    }
    __syncthreads();
    if (t < 128) {
        float2 p0 = sPart[t * 4 + 0], p1 = sPart[t * 4 + 1];
        float2 p2 = sPart[t * 4 + 2], p3 = sPart[t * 4 + 3];
        float s = p0.x + p1.x + p2.x + p3.x;
        float q = p0.y + p1.y + p2.y + p3.y;
        float mu = s * (1.0f / C);
        float var = q * (1.0f / C) - mu * mu;
        sStat[t] = make_float2(mu, rsqrtf(var + 1e-5f));
    }
    __syncthreads();

#pragma unroll
    for (int mt = 0; mt < 4; ++mt) {
#pragma unroll
        for (int hi = 0; hi < 2; ++hi) {
            int row = (wm * 4 + mt) * 16 + hi * 8 + (lane >> 2);
            int node = nodeBase + row;
            if (node < N) {
                float2 st = sStat[row];
#pragma unroll
                for (int nt = 0; nt < 4; ++nt) {
                    int col = (wn * 4 + nt) * 8 + (lane & 3) * 2;
                    float v0 = acc[mt][nt][hi * 2 + 0] + sBias[col];
                    float v1 = acc[mt][nt][hi * 2 + 1] + sBias[col + 1];
                    float2 o;
                    o.x = fmaxf((v0 - st.x) * st.y * sLnw[col]     + sLnb[col],     0.f);
                    o.y = fmaxf((v1 - st.x) * st.y * sLnw[col + 1] + sLnb[col + 1], 0.f);
                    *(float2*)(out + (size_t)node * C + col) = o;
                }
            }
        }
    }
}

// ---------------- host launcher ----------------
extern "C" void kernel_launch(void* const* d_in, const int* in_sizes, int n_in,
                              void* d_out, int out_size)
{
    const float* x_user = (const float*)d_in[0];
    const float* x_item = (const float*)d_in[1];
    const int*   ei_ui  = (const int*)d_in[2];
    const int*   ei_iu  = (const int*)d_in[3];
    const int*   ei_uu  = (const int*)d_in[4];
    const float* Wl     = (const float*)d_in[5];
    const float* bl     = (const float*)d_in[6];
    const float* Wr     = (const float*)d_in[7];
    const float* ln_w   = (const float*)d_in[8];
    const float* ln_b   = (const float*)d_in[9];
    float* out = (float*)d_out;

    void *pxu_, *pxi_, *pagg_, *pcnt_, *pinv_, *pws_;
    cudaGetSymbolAddress(&pxu_, g_xu);
    cudaGetSymbolAddress(&pxi_, g_xi);
    cudaGetSymbolAddress(&pagg_, g_agg);
    cudaGetSymbolAddress(&pcnt_, g_cnt);
    cudaGetSymbolAddress(&pinv_, g_inv);
    cudaGetSymbolAddress(&pws_, g_wsum);
    float* pxu  = (float*)pxu_;
    float* pxi  = (float*)pxi_;
    float* pagg = (float*)pagg_;
    int*   pcnt = (int*)pcnt_;
    float* pinv = (float*)pinv_;
    float* pws  = (float*)pws_;

    cudaFuncSetAttribute((const void*)gemm_mma<2>,
                         cudaFuncAttributeMaxDynamicSharedMemorySize, GEMM_SMEM);
    cudaFuncSetAttribute((const void*)gemm_mma<3>,
                         cudaFuncAttributeMaxDynamicSharedMemorySize, GEMM_SMEM);

    // degree counts (edges identical across layers -> compute once)
    zero_k<<<256, 256>>>((float4*)pcnt, (long)(3 * N_NODE) / 4);
    count_k<<<2048, 256>>>(ei_ui + NEDGE, pcnt + 0 * N_NODE, NEDGE);
    count_k<<<2048, 256>>>(ei_iu + NEDGE, pcnt + 1 * N_NODE, NEDGE);
    count_k<<<2048, 256>>>(ei_uu + NEDGE, pcnt + 2 * N_NODE, NEDGE);
    inv_k<<<(3 * N_NODE + 255) / 256, 256>>>(pcnt, pinv, 3 * N_NODE);

    // Wsum[l] = Wr[l,1] + Wr[l,2]  (fold the two xu @ Wr terms into one GEMM term)
    for (int l = 0; l < 2; ++l)
        addW_k<<<(CC + 255) / 256, 256>>>(Wr + (size_t)(l * 3 + 1) * CC,
                                          Wr + (size_t)(l * 3 + 2) * CC,
                                          pws + (size_t)l * CC, CC);

    for (int l = 0; l < 2; ++l) {
        const float* xu_src = (l == 0) ? x_user : pxu;
        const float* xi_src = (l == 0) ? x_item : pxi;
        float* outu = (l == 0) ? pxu : out;
        float* outi = (l == 0) ? pxi : out + NC;

        // zero all three agg buffers
        zero_k<<<4096, 256>>>((float4*)pagg, (long)(3 * NC) / 4);

        // scatter per edge type
        scatter_k<<<8192, 256>>>(xu_src, ei_ui, pagg + 0 * NC, NEDGE);  // user->item
        scatter_k<<<8192, 256>>>(xi_src, ei_iu, pagg + 1 * NC, NEDGE);  // item->user
        scatter_k<<<8192, 256>>>(xu_src, ei_uu, pagg + 2 * NC, NEDGE);  // user->user

        // item: mean_ui @ Wl[l,0] + bl[l,0] + xi @ Wr[l,0] -> LN(item) -> ReLU
        gemm_mma<2><<<GEMM_GRID, 256, GEMM_SMEM>>>(
            pagg + 0 * NC, pinv + 0 * N_NODE, Wl + (size_t)(l * 3 + 0) * CC,
            xi_src,        nullptr,           Wr + (size_t)(l * 3 + 0) * CC,
            nullptr, nullptr, nullptr,
            bl + (size_t)(l * 3 + 0) * C, nullptr,
            ln_w + (size_t)(l * 2 + 1) * C, ln_b + (size_t)(l * 2 + 1) * C,
            outi, N_NODE);

        // user: mean_iu@Wl[l,1] + mean_uu@Wl[l,2] + xu@(Wr[l,1]+Wr[l,2]) + bl[l,1]+bl[l,2]
        gemm_mma<3><<<GEMM_GRID, 256, GEMM_SMEM>>>(
            pagg + 1 * NC, pinv + 1 * N_NODE, Wl + (size_t)(l * 3 + 1) * CC,
            pagg + 2 * NC, pinv + 2 * N_NODE, Wl + (size_t)(l * 3 + 2) * CC,
            xu_src,        nullptr,           pws + (size_t)l * CC,
            bl + (size_t)(l * 3 + 1) * C, bl + (size_t)(l * 3 + 2) * C,
            ln_w + (size_t)(l * 2 + 0) * C, ln_b + (size_t)(l * 2 + 0) * C,
            outu, N_NODE);
    }
}